// round 6
// baseline (speedup 1.0000x reference)
#include <cuda_runtime.h>
#include <cuda_fp16.h>
#include <math.h>

// Problem constants
#define NB 64
#define NS 512
#define NPIX (NS * NS)          // 262144
#define HF_COUNT 245760.0f      // 512*512 - 128*128
#define NBLK2 (128 * NB)        // fft2 block count = 8192

// -------- scratch (device globals; no allocation allowed) --------
__device__ __half2 g_Bf[NB * NPIX];  // 67 MB: pass-1 output (fp16 complex), TRANSPOSED
__device__ float2  g_tw[512];        // twiddles w^k = exp(-2*pi*i*k/512)
__device__ float   g_part[NB][256];  // per-(batch, v-pair) partial sums (deterministic)
__device__ unsigned g_counter;       // fft2 completion counter (reset every launch)

// -------- packed f32x2 complex helpers (sm_103a FFMA2 path) --------
typedef unsigned long long c64;      // (re, im) packed as 2 x f32

static __device__ __forceinline__ c64 f2add(c64 a, c64 b) {
    c64 r; asm("add.rn.f32x2 %0, %1, %2;" : "=l"(r) : "l"(a), "l"(b)); return r;
}
static __device__ __forceinline__ c64 f2mul(c64 a, c64 b) {
    c64 r; asm("mul.rn.f32x2 %0, %1, %2;" : "=l"(r) : "l"(a), "l"(b)); return r;
}
static __device__ __forceinline__ c64 f2fma(c64 a, c64 b, c64 c) {
    c64 r; asm("fma.rn.f32x2 %0, %1, %2, %3;" : "=l"(r) : "l"(a), "l"(b), "l"(c)); return r;
}
static __device__ __forceinline__ c64 cpack2(float x, float y) {
    c64 r; asm("mov.b64 %0, {%1, %2};" : "=l"(r) : "f"(x), "f"(y)); return r;
}
static __device__ __forceinline__ float2 cunpk(c64 a) {
    float2 r; asm("mov.b64 {%0, %1}, %2;" : "=f"(r.x), "=f"(r.y) : "l"(a)); return r;
}
static __device__ __forceinline__ c64 cswap(c64 a) {   // (x,y) -> (y,x)
    float2 t = cunpk(a); return cpack2(t.y, t.x);
}

struct PCst { c64 M1, PM, RR, RmR, mRmR; };
static __device__ __forceinline__ PCst make_cst() {
    const float r = 0.70710678118654752440f;
    PCst c;
    c.M1   = cpack2(-1.0f, -1.0f);
    c.PM   = cpack2( 1.0f, -1.0f);
    c.RR   = cpack2( r,  r);
    c.RmR  = cpack2( r, -r);
    c.mRmR = cpack2(-r, -r);
    return c;
}

// csub(a,b) = fma(b, (-1,-1), a)
#define F2SUB(a, b) f2fma((b), C.M1, (a))
// mul by -i: (x,y)->(y,-x)
#define F2NI(a) f2mul(cswap(a), C.PM)

// cmul with dual twiddle tables: wxx=(wx,wx), wyy=(-wy,wy)
static __device__ __forceinline__ c64 cmulp(c64 a, c64 wxx, c64 wyy) {
    return f2fma(cswap(a), wyy, f2mul(a, wxx));
}

// DFT-8 (DIF internally, output in natural order X[0..7]), packed f32x2
static __device__ __forceinline__ void dft8p(const c64 a[8], c64 X[8], const PCst& C) {
    c64 s0 = f2add(a[0], a[4]), d0 = F2SUB(a[0], a[4]);
    c64 s1 = f2add(a[1], a[5]), d1 = F2SUB(a[1], a[5]);
    c64 s2 = f2add(a[2], a[6]), d2 = F2SUB(a[2], a[6]);
    c64 s3 = f2add(a[3], a[7]), d3 = F2SUB(a[3], a[7]);
    // d1t = w8^1 * d1 = (r(x+y), r(y-x))
    c64 d1t = f2fma(cswap(d1), C.RmR, f2mul(d1, C.RR));
    // d2t = -i * d2
    c64 d2t = F2NI(d2);
    // d3t = w8^3 * d3 = (r(y-x), -r(x+y))
    c64 d3t = f2fma(cswap(d3), C.RmR, f2mul(d3, C.mRmR));
    // even DFT4
    c64 u0 = f2add(s0, s2), u2 = F2SUB(s0, s2);
    c64 u1 = f2add(s1, s3), u3t = F2SUB(s1, s3);
    c64 u3 = F2NI(u3t);
    X[0] = f2add(u0, u1);  X[4] = F2SUB(u0, u1);
    X[2] = f2add(u2, u3);  X[6] = F2SUB(u2, u3);
    // odd DFT4
    c64 v0 = f2add(d0, d2t), v2 = F2SUB(d0, d2t);
    c64 v1 = f2add(d1t, d3t), v3t = F2SUB(d1t, d3t);
    c64 v3 = F2NI(v3t);
    X[1] = f2add(v0, v1);  X[5] = F2SUB(v0, v1);
    X[3] = f2add(v2, v3);  X[7] = F2SUB(v2, v3);
}

static __device__ __forceinline__ float gray01(float r, float g, float b) {
    return (r * 0.299f + g * 0.587f + b * 0.114f + 1.0f) * 0.5f;
}

// named sub-barrier: 64 threads
#define BARS(id) asm volatile("bar.sync %0, 64;" :: "r"(id) : "memory")

// -------- K0: twiddle table init + counter reset --------
__global__ void k_init() {
    int t = threadIdx.x;
    double ang = -6.2831853071795864769252867665590058 * (double)t / 512.0;
    g_tw[t] = make_float2((float)cos(ang), (float)sin(ang));
    if (t == 0) g_counter = 0u;
}

#define PADIDX(i) ((i) + ((i) >> 3))

// -------- K1: fused gray + row-FFT + transposed fp16 write --------
// 8 FFTs (8 consecutive image rows of one batch) per 512-thread block.
__global__ void __launch_bounds__(512) k_fft1(const float* __restrict__ gen,
                                              const float* __restrict__ tgt) {
    __shared__ c64 twA[512], twB[512];
    __shared__ c64 buf[8][576];   // reused as tile[512][9] at the end

    int tid = threadIdx.x;
    { float2 w = g_tw[tid]; twA[tid] = cpack2(w.x, w.x); twB[tid] = cpack2(-w.y, w.y); }
    PCst C = make_cst();

    int f = tid >> 6;                 // FFT id within block (0..7)
    int j = tid & 63;                 // lane within FFT
    int b  = blockIdx.x >> 6;         // 64 blocks per batch
    int y0 = (blockIdx.x & 63) << 3;  // first image row of this block
    int y  = y0 + f;

    size_t gbase = (size_t)b * (3u * NPIX) + (size_t)y * NS;
    const float* gp = gen + gbase;
    const float* tp = tgt + gbase;

    c64 a[8], X[8];
    #pragma unroll
    for (int p = 0; p < 8; p++) {
        int x = p * 64 + j;
        float g0 = gp[x], g1 = gp[x + NPIX], g2 = gp[x + 2 * NPIX];
        float t0 = tp[x], t1 = tp[x + NPIX], t2 = tp[x + 2 * NPIX];
        a[p] = cpack2(gray01(g0, g1, g2), gray01(t0, t1, t2));
    }

    // stage 0 (L=1)
    dft8p(a, X, C);
    #pragma unroll
    for (int q = 0; q < 8; q++) { int idx = j * 8 + q; buf[f][PADIDX(idx)] = X[q]; }
    __syncthreads();   // full: covers twiddle tables + stage0 exchange

    // stage 1 (L=8) — buf[f] is 64-thread-group private: named barriers suffice
    #pragma unroll
    for (int p = 0; p < 8; p++) { int idx = p * 64 + j; a[p] = buf[f][PADIDX(idx)]; }
    BARS(1 + f);
    int k1 = j & 7, b1 = j >> 3;
    #pragma unroll
    for (int p = 1; p < 8; p++) a[p] = cmulp(a[p], twA[(p * k1) << 3], twB[(p * k1) << 3]);
    dft8p(a, X, C);
    #pragma unroll
    for (int q = 0; q < 8; q++) { int idx = b1 * 64 + q * 8 + k1; buf[f][PADIDX(idx)] = X[q]; }
    BARS(1 + f);

    // stage 2 (L=64)
    #pragma unroll
    for (int p = 0; p < 8; p++) { int idx = p * 64 + j; a[p] = buf[f][PADIDX(idx)]; }
    __syncthreads();   // full: tile below spans all groups' buf regions
    #pragma unroll
    for (int p = 1; p < 8; p++) a[p] = cmulp(a[p], twA[p * j], twB[p * j]);
    dft8p(a, X, C);

    // stage result into transpose tile: tile[u][f], padded stride 9
    c64* tile = &buf[0][0];
    #pragma unroll
    for (int q = 0; q < 8; q++) { int u = q * 64 + j; tile[u * 9 + f] = X[q]; }
    __syncthreads();

    // coalesced transposed fp16 write: 8 consecutive y per u = 32B sector
    int yo = tid & 7;          // y offset within block
    int ub = tid >> 3;         // 0..63
    __half2* dst = g_Bf + (size_t)b * NPIX + y0 + yo;
    #pragma unroll
    for (int i = 0; i < 8; i++) {
        int u = ub + i * 64;
        float2 z = cunpk(tile[u * 9 + yo]);
        dst[(size_t)u * NS] = __floats2half2_rn(z.x, z.y);
    }
}

// -------- K2: column FFT on conjugate-partner row pairs + fused PSD + fused finalize --------
// 256 threads, 2 v-pairs (4 row FFTs) per block. grid (128, NB).
__global__ void __launch_bounds__(256) k_fft2_psd(float* __restrict__ out) {
    __shared__ c64 twA[512], twB[512];
    __shared__ c64 buf2[4][576];   // 18432 B; reused as res[4][512], then as final scratch
    __shared__ float wsum[8];
    __shared__ unsigned s_old;

    int tid = threadIdx.x;
    #pragma unroll
    for (int i = 0; i < 2; i++) {
        int k = tid + i * 256;
        float2 w = g_tw[k];
        twA[k] = cpack2(w.x, w.x); twB[k] = cpack2(-w.y, w.y);
    }
    PCst C = make_cst();

    int s    = tid >> 7;           // sub-block (pair) 0..1
    int tid2 = tid & 127;
    int f    = tid2 >> 6;          // 0 or 1 within pair
    int j    = tid2 & 63;
    int grp  = s * 2 + f;          // 64-thread group id 0..3
    int b    = blockIdx.y;
    int v    = blockIdx.x * 2 + s; // 0..255
    int rA = v;
    int rB = (v == 0) ? 256 : 512 - v;
    int r  = f ? rB : rA;
    c64* buf = &buf2[grp][0];
    c64* res = &buf2[0][0];        // res[(grp)*512 + e]

    const __half2* rp = g_Bf + (size_t)b * NPIX + (size_t)r * NS;

    c64 a[8], X[8];
    #pragma unroll
    for (int p = 0; p < 8; p++) {
        float2 z = __half22float2(rp[p * 64 + j]);
        a[p] = cpack2(z.x, z.y);
    }

    dft8p(a, X, C);
    #pragma unroll
    for (int q = 0; q < 8; q++) { int idx = j * 8 + q; buf[PADIDX(idx)] = X[q]; }
    __syncthreads();   // full: covers twiddle tables + stage0 exchange

    #pragma unroll
    for (int p = 0; p < 8; p++) { int idx = p * 64 + j; a[p] = buf[PADIDX(idx)]; }
    BARS(1 + grp);
    int k1 = j & 7, b1 = j >> 3;
    #pragma unroll
    for (int p = 1; p < 8; p++) a[p] = cmulp(a[p], twA[(p * k1) << 3], twB[(p * k1) << 3]);
    dft8p(a, X, C);
    #pragma unroll
    for (int q = 0; q < 8; q++) { int idx = b1 * 64 + q * 8 + k1; buf[PADIDX(idx)] = X[q]; }
    BARS(1 + grp);

    #pragma unroll
    for (int p = 0; p < 8; p++) { int idx = p * 64 + j; a[p] = buf[PADIDX(idx)]; }
    __syncthreads();   // full: res overwrite spans all groups' buf regions
    #pragma unroll
    for (int p = 1; p < 8; p++) a[p] = cmulp(a[p], twA[p * j], twB[p * j]);
    dft8p(a, X, C);
    #pragma unroll
    for (int q = 0; q < 8; q++) res[grp * 512 + q * 64 + j] = X[q];
    __syncthreads();

    // PSD pairing: Z(u,e) with Z(512-u, 512-e); both rows of this pair in res.
    bool self = (v == 0);
    bool lowA = (rA < 64) | (rA >= 448);
    bool lowB = (rB < 64) | (rB >= 448);

    float acc = 0.0f;
    #pragma unroll
    for (int it = 0; it < 8; it++) {
        int i = it * 128 + tid2;       // 0..1023 over the pair's 2 rows
        int h = i >> 9;                // 0 -> row rA, 1 -> row rB
        int e = i & 511;               // y-frequency
        bool lowr = h ? lowB : lowA;
        bool lowe = (e < 64) | (e >= 448);
        if (lowr & lowe) continue;     // low-frequency box masked out

        float2 z1 = cunpk(res[(s * 2 + h) * 512 + e]);
        int ps = self ? h : (1 - h);
        float2 z2 = cunpk(res[(s * 2 + ps) * 512 + ((512 - e) & 511)]);

        float ra = 0.5f * (z1.x + z2.x), ia = 0.5f * (z1.y - z2.y);
        float rb = 0.5f * (z1.y + z2.y), ib = 0.5f * (z2.x - z1.x);
        float pa = fmaf(ra, ra, ia * ia) + 1e-10f;
        float pb = fmaf(rb, rb, ib * ib) + 1e-10f;
        acc += __log2f(pa) - __log2f(pb);   // log10 factor applied at the end
    }

    // warp reduce (fixed order -> deterministic), then 4 warps per sub-block
    #pragma unroll
    for (int o = 16; o > 0; o >>= 1) acc += __shfl_down_sync(0xFFFFFFFFu, acc, o);
    if ((tid & 31) == 0) wsum[tid >> 5] = acc;
    __syncthreads();
    if (tid < 2) {
        int ss = tid;
        float d = wsum[ss * 4] + wsum[ss * 4 + 1] + wsum[ss * 4 + 2] + wsum[ss * 4 + 3];
        g_part[b][blockIdx.x * 2 + ss] = d;   // no atomics -> deterministic values
    }

    // ---- fused finalize: last-done block reduces g_part ----
    __threadfence();
    if (tid == 0) s_old = atomicAdd(&g_counter, 1u);
    __syncthreads();
    if (s_old == NBLK2 - 1u) {
        float* fbuf = (float*)&buf2[0][0];   // res no longer needed
        int bb = tid >> 2, q = tid & 3;      // 4 threads per batch
        float sum = 0.0f;
        #pragma unroll 16
        for (int k = 0; k < 64; k++) sum += __ldcg(&g_part[bb][q * 64 + k]);
        fbuf[bb * 5 + q] = sum;
        __syncthreads();
        float* red = fbuf + 512;
        if (tid < 64) {
            float d = fbuf[tid * 5] + fbuf[tid * 5 + 1] + fbuf[tid * 5 + 2] + fbuf[tid * 5 + 3];
            red[tid] = fabsf(d);
        }
        __syncthreads();
        #pragma unroll
        for (int s2 = 32; s2 > 0; s2 >>= 1) {
            if (tid < s2) red[tid] += red[tid + s2];
            __syncthreads();
        }
        if (tid == 0) out[0] = red[0] * (0.30102999566398119521f / (HF_COUNT * 64.0f));
    }
}

// -------- launch --------
extern "C" void kernel_launch(void* const* d_in, const int* in_sizes, int n_in,
                              void* d_out, int out_size) {
    const float* gen = (const float*)d_in[0];
    const float* tgt = (const float*)d_in[1];
    float* out = (float*)d_out;
    (void)in_sizes; (void)n_in; (void)out_size;

    k_init<<<1, 512>>>();
    k_fft1<<<NB * 64, 512>>>(gen, tgt);        // fused gray + row FFT + transpose
    {
        dim3 g(128, NB);
        k_fft2_psd<<<g, 256>>>(out);           // column FFT + PSD + finalize
    }
}

// round 7
// speedup vs baseline: 1.2361x; 1.2361x over previous
#include <cuda_runtime.h>
#include <cuda_fp16.h>
#include <math.h>

// Problem constants
#define NB 64
#define NS 512
#define NPIX (NS * NS)          // 262144
#define HF_COUNT 245760.0f      // 512*512 - 128*128
#define NBLK2 (128 * NB)        // fft2 block count = 8192

// -------- scratch (device globals; no allocation allowed) --------
__device__ __half2 g_Bf[NB * NPIX];  // 67 MB: pass-1 output (fp16 complex), TRANSPOSED
__device__ float2  g_tw[512];        // twiddles w^k = exp(-2*pi*i*k/512)
__device__ float   g_part[NB][256];  // per-(batch, v-pair) partial sums (deterministic)
__device__ unsigned g_counter;       // fft2 completion counter (reset every launch)

// -------- complex helpers --------
static __device__ __forceinline__ float2 cadd(float2 a, float2 b) { return make_float2(a.x + b.x, a.y + b.y); }
static __device__ __forceinline__ float2 csub(float2 a, float2 b) { return make_float2(a.x - b.x, a.y - b.y); }
static __device__ __forceinline__ float2 cmul(float2 a, float2 w) {
    return make_float2(fmaf(a.x, w.x, -a.y * w.y), fmaf(a.x, w.y, a.y * w.x));
}

// DFT-8 (DIF internally, output in natural order X[0..7])
static __device__ __forceinline__ void dft8(const float2 a[8], float2 X[8]) {
    const float r = 0.70710678118654752440f;
    float2 s0 = cadd(a[0], a[4]), d0 = csub(a[0], a[4]);
    float2 s1 = cadd(a[1], a[5]), d1 = csub(a[1], a[5]);
    float2 s2 = cadd(a[2], a[6]), d2 = csub(a[2], a[6]);
    float2 s3 = cadd(a[3], a[7]), d3 = csub(a[3], a[7]);
    float2 d1t = make_float2(r * (d1.x + d1.y), r * (d1.y - d1.x));
    float2 d2t = make_float2(d2.y, -d2.x);
    float2 d3t = make_float2(r * (d3.y - d3.x), -r * (d3.x + d3.y));
    float2 u0 = cadd(s0, s2), u2 = csub(s0, s2);
    float2 u1 = cadd(s1, s3);
    float2 u3t = csub(s1, s3);
    float2 u3 = make_float2(u3t.y, -u3t.x);
    X[0] = cadd(u0, u1);  X[4] = csub(u0, u1);
    X[2] = cadd(u2, u3);  X[6] = csub(u2, u3);
    float2 v0 = cadd(d0, d2t), v2 = csub(d0, d2t);
    float2 v1 = cadd(d1t, d3t);
    float2 v3t = csub(d1t, d3t);
    float2 v3 = make_float2(v3t.y, -v3t.x);
    X[1] = cadd(v0, v1);  X[5] = csub(v0, v1);
    X[3] = cadd(v2, v3);  X[7] = csub(v2, v3);
}

static __device__ __forceinline__ float gray01(float r, float g, float b) {
    return (r * 0.299f + g * 0.587f + b * 0.114f + 1.0f) * 0.5f;
}

// -------- K0: twiddle table init (fast float path) + counter reset --------
__global__ void k_init() {
    int t = threadIdx.x;
    float s, c;
    sincospif((float)t * (1.0f / 256.0f), &s, &c);   // w^t = cos - i*sin
    g_tw[t] = make_float2(c, -s);
    if (t == 0) g_counter = 0u;
}

#define PADIDX(i) ((i) + ((i) >> 3))

// -------- K1: fused gray + row-FFT + transposed fp16 write --------
// 8 FFTs (8 consecutive image rows of one batch) per 512-thread block.
__global__ void __launch_bounds__(512) k_fft1(const float* __restrict__ gen,
                                              const float* __restrict__ tgt) {
    __shared__ float2 tw[512];
    __shared__ float2 buf[8][576];   // 4608 float2; reused as tile[512][9] at the end

    int tid = threadIdx.x;
    tw[tid] = g_tw[tid];

    int f = tid >> 6;                 // FFT id within block (0..7)
    int j = tid & 63;                 // lane within FFT
    int b  = blockIdx.x >> 6;         // 64 blocks per batch
    int y0 = (blockIdx.x & 63) << 3;  // first image row of this block
    int y  = y0 + f;

    size_t gbase = (size_t)b * (3u * NPIX) + (size_t)y * NS;
    const float* gp = gen + gbase;
    const float* tp = tgt + gbase;

    float2 a[8], X[8];
    #pragma unroll
    for (int p = 0; p < 8; p++) {
        int x = p * 64 + j;
        float g0 = gp[x], g1 = gp[x + NPIX], g2 = gp[x + 2 * NPIX];
        float t0 = tp[x], t1 = tp[x + NPIX], t2 = tp[x + 2 * NPIX];
        a[p] = make_float2(gray01(g0, g1, g2), gray01(t0, t1, t2));
    }

    // stage 0 (L=1)
    dft8(a, X);
    #pragma unroll
    for (int q = 0; q < 8; q++) { int idx = j * 8 + q; buf[f][PADIDX(idx)] = X[q]; }
    __syncthreads();   // also covers twiddle table fill

    // stage 1 (L=8)
    #pragma unroll
    for (int p = 0; p < 8; p++) { int idx = p * 64 + j; a[p] = buf[f][PADIDX(idx)]; }
    __syncthreads();
    int k1 = j & 7, b1 = j >> 3;
    #pragma unroll
    for (int p = 1; p < 8; p++) a[p] = cmul(a[p], tw[(p * k1) << 3]);
    dft8(a, X);
    #pragma unroll
    for (int q = 0; q < 8; q++) { int idx = b1 * 64 + q * 8 + k1; buf[f][PADIDX(idx)] = X[q]; }
    __syncthreads();

    // stage 2 (L=64)
    #pragma unroll
    for (int p = 0; p < 8; p++) { int idx = p * 64 + j; a[p] = buf[f][PADIDX(idx)]; }
    __syncthreads();   // all buf reads done; safe to reuse as transpose tile
    #pragma unroll
    for (int p = 1; p < 8; p++) a[p] = cmul(a[p], tw[p * j]);
    dft8(a, X);

    // stage result into transpose tile: tile[u][f], padded stride 9
    float2* tile = &buf[0][0];
    #pragma unroll
    for (int q = 0; q < 8; q++) { int u = q * 64 + j; tile[u * 9 + f] = X[q]; }
    __syncthreads();

    // coalesced transposed fp16 write: 8 consecutive y per u = 32B sector
    int yo = tid & 7;          // y offset within block
    int ub = tid >> 3;         // 0..63
    __half2* dst = g_Bf + (size_t)b * NPIX + y0 + yo;
    #pragma unroll
    for (int i = 0; i < 8; i++) {
        int u = ub + i * 64;
        float2 z = tile[u * 9 + yo];
        dst[(size_t)u * NS] = __floats2half2_rn(z.x, z.y);
    }
}

// -------- K2: column FFT on conjugate-partner row pairs + fused PSD + fused finalize --------
// 256 threads, 2 v-pairs (4 row FFTs) per block. grid (128, NB).
__global__ void __launch_bounds__(256) k_fft2_psd(float* __restrict__ out) {
    __shared__ float2 tw[512];
    __shared__ float2 buf2[4][576];   // 18432 B; reused as res[4][512], then final scratch
    __shared__ float  wsum[8];
    __shared__ unsigned s_old;

    int tid = threadIdx.x;
    tw[tid] = g_tw[tid];
    tw[tid + 256] = g_tw[tid + 256];

    int s    = tid >> 7;           // sub-block (pair) 0..1
    int tid2 = tid & 127;
    int f    = tid2 >> 6;          // 0 or 1 within pair
    int j    = tid2 & 63;
    int b    = blockIdx.y;
    int v    = blockIdx.x * 2 + s; // 0..255
    int rA = v;
    int rB = (v == 0) ? 256 : 512 - v;
    int r  = f ? rB : rA;
    float2* buf = &buf2[s * 2 + f][0];
    float2* res = &buf2[0][0];     // res[(s*2+h)*512 + e]

    const __half2* rp = g_Bf + (size_t)b * NPIX + (size_t)r * NS;

    float2 a[8], X[8];
    #pragma unroll
    for (int p = 0; p < 8; p++) a[p] = __half22float2(rp[p * 64 + j]);

    dft8(a, X);
    #pragma unroll
    for (int q = 0; q < 8; q++) { int idx = j * 8 + q; buf[PADIDX(idx)] = X[q]; }
    __syncthreads();

    #pragma unroll
    for (int p = 0; p < 8; p++) { int idx = p * 64 + j; a[p] = buf[PADIDX(idx)]; }
    __syncthreads();
    int k1 = j & 7, b1 = j >> 3;
    #pragma unroll
    for (int p = 1; p < 8; p++) a[p] = cmul(a[p], tw[(p * k1) << 3]);
    dft8(a, X);
    #pragma unroll
    for (int q = 0; q < 8; q++) { int idx = b1 * 64 + q * 8 + k1; buf[PADIDX(idx)] = X[q]; }
    __syncthreads();

    #pragma unroll
    for (int p = 0; p < 8; p++) { int idx = p * 64 + j; a[p] = buf[PADIDX(idx)]; }
    __syncthreads();   // all buf reads done; safe to overwrite as res
    #pragma unroll
    for (int p = 1; p < 8; p++) a[p] = cmul(a[p], tw[p * j]);
    dft8(a, X);
    #pragma unroll
    for (int q = 0; q < 8; q++) res[(s * 2 + f) * 512 + q * 64 + j] = X[q];
    __syncthreads();

    // PSD pairing: Z(u,e) with Z(512-u, 512-e); both rows of this pair in res.
    bool self = (v == 0);
    bool lowA = (rA < 64) | (rA >= 448);
    bool lowB = (rB < 64) | (rB >= 448);

    float acc = 0.0f;
    #pragma unroll
    for (int it = 0; it < 8; it++) {
        int i = it * 128 + tid2;       // 0..1023 over the pair's 2 rows
        int h = i >> 9;                // 0 -> row rA, 1 -> row rB
        int e = i & 511;               // y-frequency
        bool lowr = h ? lowB : lowA;
        bool lowe = (e < 64) | (e >= 448);
        if (lowr & lowe) continue;     // low-frequency box masked out

        float2 z1 = res[(s * 2 + h) * 512 + e];
        int ps = self ? h : (1 - h);
        float2 z2 = res[(s * 2 + ps) * 512 + ((512 - e) & 511)];

        float ra = 0.5f * (z1.x + z2.x), ia = 0.5f * (z1.y - z2.y);
        float rb = 0.5f * (z1.y + z2.y), ib = 0.5f * (z2.x - z1.x);
        float pa = fmaf(ra, ra, ia * ia) + 1e-10f;
        float pb = fmaf(rb, rb, ib * ib) + 1e-10f;
        acc += __log2f(pa) - __log2f(pb);   // log10 factor applied at the end
    }

    // warp reduce (fixed order -> deterministic), then 4 warps per sub-block
    #pragma unroll
    for (int o = 16; o > 0; o >>= 1) acc += __shfl_down_sync(0xFFFFFFFFu, acc, o);
    if ((tid & 31) == 0) wsum[tid >> 5] = acc;
    __syncthreads();
    if (tid < 2) {
        int ss = tid;
        float d = wsum[ss * 4] + wsum[ss * 4 + 1] + wsum[ss * 4 + 2] + wsum[ss * 4 + 3];
        g_part[b][blockIdx.x * 2 + ss] = d;   // no atomics -> deterministic values
    }

    // ---- fused finalize: last-done block reduces g_part (fixed-order sums) ----
    __threadfence();
    if (tid == 0) s_old = atomicAdd(&g_counter, 1u);
    __syncthreads();
    if (s_old == NBLK2 - 1u) {
        float* fbuf = (float*)&buf2[0][0];   // res no longer needed
        int bb = tid >> 2, q = tid & 3;      // 4 threads per batch
        float sum = 0.0f;
        #pragma unroll 16
        for (int k = 0; k < 64; k++) sum += __ldcg(&g_part[bb][q * 64 + k]);
        fbuf[bb * 5 + q] = sum;
        __syncthreads();
        float* red = fbuf + 512;
        if (tid < 64) {
            float d = fbuf[tid * 5] + fbuf[tid * 5 + 1] + fbuf[tid * 5 + 2] + fbuf[tid * 5 + 3];
            red[tid] = fabsf(d);
        }
        __syncthreads();
        #pragma unroll
        for (int s2 = 32; s2 > 0; s2 >>= 1) {
            if (tid < s2) red[tid] += red[tid + s2];
            __syncthreads();
        }
        if (tid == 0) out[0] = red[0] * (0.30102999566398119521f / (HF_COUNT * 64.0f));
    }
}

// -------- launch --------
extern "C" void kernel_launch(void* const* d_in, const int* in_sizes, int n_in,
                              void* d_out, int out_size) {
    const float* gen = (const float*)d_in[0];
    const float* tgt = (const float*)d_in[1];
    float* out = (float*)d_out;
    (void)in_sizes; (void)n_in; (void)out_size;

    k_init<<<1, 512>>>();
    k_fft1<<<NB * 64, 512>>>(gen, tgt);        // fused gray + row FFT + transpose
    {
        dim3 g(128, NB);
        k_fft2_psd<<<g, 256>>>(out);           // column FFT + PSD + finalize
    }
}